// round 3
// baseline (speedup 1.0000x reference)
#include <cuda_runtime.h>

#define GAMMA    0.99f
#define B_ROWS   8192
#define T1       1025
#define NSCAN    1023
#define THREADS  128
#define ITEMS    8                       // 128*8 = 1024 >= 1023
#define SKEW(j)  ((j) + ((j) >> 3))      // +1 pad per 8 floats -> stride-8 reads conflict-free
#define SMEMN    (T1 + (T1 >> 3) + 2)    // 1025 + 128 + 2

__device__ float        g_partial[B_ROWS];
__device__ unsigned int g_count = 0;     // self-resetting; graph-replay safe

// One block per row.
// Backward recurrence y[t] = b[t] + a[t]*y[t+1], y[1023] = Q[1024], scan order s=0..1022, t=1022-s.
//   a[t] = GAMMA * c(t+2),  b[t] = rew[t+1] + GAMMA*(eTQ[t+2] - c(t+2)*tQ[t+2])
//   c(j) = exp(min(tpp[j]-bpp[j], 0))
__global__ __launch_bounds__(THREADS)
void retrace_kernel(const float* __restrict__ Q,
                    const float* __restrict__ eTQ,
                    const float* __restrict__ tQ,
                    const float* __restrict__ rew,
                    const float* __restrict__ tpp,
                    const float* __restrict__ bpp,
                    float* __restrict__ out)
{
    __shared__ float  sc[SMEMN];    // GAMMA * c(j)
    __shared__ float  se[SMEMN];    // GAMMA * (eTQ[j] - c(j)*tQ[j])
    __shared__ float  srw[SMEMN];   // rew[j]
    __shared__ float  sq[SMEMN];    // Q[j]
    __shared__ float  wAs[4], wBs[4], werr[4];
    __shared__ double dred[THREADS];
    __shared__ bool   isLast;

    const int  row  = blockIdx.x;
    const int  tid  = threadIdx.x;
    const long base = (long)row * T1;

    // ---- Stage: forward, fully-coalesced loads; fold exp/c math in here ----
    for (int j = tid; j < T1; j += THREADS) {
        const float tp = tpp[base + j];
        const float bp = bpp[base + j];
        const float c  = __expf(fminf(tp - bp, 0.0f));
        const int   ji = SKEW(j);
        sc[ji]  = GAMMA * c;
        se[ji]  = GAMMA * (eTQ[base + j] - c * tQ[base + j]);
        srw[ji] = rew[base + j];
        sq[ji]  = Q[base + j];
    }
    __syncthreads();

    // ---- Phase 1: per-thread chunk of 8 scan items, compose into one affine ----
    float a[ITEMS], b[ITEMS];
    float A = 1.0f, Bc = 0.0f;
    #pragma unroll
    for (int k = 0; k < ITEMS; k++) {
        const int s = tid * ITEMS + k;
        if (s < NSCAN) {
            const int j = 1024 - s;               // j = t+2
            a[k] = sc[SKEW(j)];
            b[k] = srw[SKEW(j - 1)] + se[SKEW(j)];
        } else {                                   // identity pad (s == 1023)
            a[k] = 1.0f; b[k] = 0.0f;
        }
        Bc = fmaf(a[k], Bc, b[k]);                 // (A,B) <- f_k  o  (A,B)
        A  = a[k] * A;
    }

    // ---- Warp-level inclusive scan of affines (5 shfl steps) ----
    const int lane = tid & 31;
    const int warp = tid >> 5;
    #pragma unroll
    for (int off = 1; off < 32; off <<= 1) {
        const float pA = __shfl_up_sync(0xffffffffu, A,  off);
        const float pB = __shfl_up_sync(0xffffffffu, Bc, off);
        if (lane >= off) { Bc = fmaf(A, pB, Bc); A *= pA; }
    }
    if (lane == 31) { wAs[warp] = A; wBs[warp] = Bc; }
    __syncthreads();

    // Cross-warp exclusive prefix (<= 3 folds, in order: deterministic)
    float WA = 1.0f, WB = 0.0f;
    for (int i = 0; i < warp; i++) { WB = fmaf(wAs[i], WB, wBs[i]); WA = wAs[i] * WA; }

    // Thread-exclusive prefix = (within-warp exclusive) o (warp prefix)
    float eA = __shfl_up_sync(0xffffffffu, A,  1);
    float eB = __shfl_up_sync(0xffffffffu, Bc, 1);
    if (lane == 0) { eA = 1.0f; eB = 0.0f; }
    const float Aex = eA * WA;
    const float Bex = fmaf(eA, WB, eB);

    // ---- Phase 2: replay chunk from seed, accumulate squared error ----
    const float init = sq[SKEW(1024)];
    float y = fmaf(Aex, init, Bex);               // = Q_ret[1023 - 8*tid]

    float err = 0.0f;
    if (tid == 0) {                               // t = 1023 term: Q_ret = init
        const float d = sq[SKEW(1023)] - init;
        err = d * d;
    }
    #pragma unroll
    for (int k = 0; k < ITEMS; k++) {
        const int s = tid * ITEMS + k;
        y = fmaf(a[k], y, b[k]);                  // y = Q_ret[1022 - s]
        if (s < NSCAN) {
            const float d = sq[SKEW(1022 - s)] - y;
            err = fmaf(d, d, err);
        }
    }

    // ---- Block error reduction (deterministic) ----
    #pragma unroll
    for (int off = 16; off; off >>= 1)
        err += __shfl_xor_sync(0xffffffffu, err, off);
    if (lane == 0) werr[warp] = err;
    __syncthreads();

    if (tid == 0) {
        g_partial[row] = (werr[0] + werr[1]) + (werr[2] + werr[3]);
        __threadfence();
        const unsigned old = atomicAdd(&g_count, 1u);
        isLast = (old == (unsigned)(gridDim.x - 1));
    }
    __syncthreads();

    // ---- Last block: deterministic final mean (fixed order), reset counter ----
    if (isLast) {
        double s = 0.0;
        for (int i = tid; i < B_ROWS; i += THREADS)
            s += (double)__ldcg(&g_partial[i]);
        dred[tid] = s;
        __syncthreads();
        #pragma unroll
        for (int off = THREADS / 2; off; off >>= 1) {
            if (tid < off) dred[tid] += dred[tid + off];
            __syncthreads();
        }
        if (tid == 0) {
            out[0]  = (float)(dred[0] / ((double)B_ROWS * 1024.0));
            g_count = 0;                          // reset for next graph replay
        }
    }
}

extern "C" void kernel_launch(void* const* d_in, const int* in_sizes, int n_in,
                              void* d_out, int out_size)
{
    (void)in_sizes; (void)n_in; (void)out_size;
    const float* Q   = (const float*)d_in[0];
    const float* eTQ = (const float*)d_in[1];
    const float* tQ  = (const float*)d_in[2];
    const float* rew = (const float*)d_in[3];
    const float* tpp = (const float*)d_in[4];
    const float* bpp = (const float*)d_in[5];

    retrace_kernel<<<B_ROWS, THREADS>>>(Q, eTQ, tQ, rew, tpp, bpp, (float*)d_out);
}

// round 4
// speedup vs baseline: 1.0104x; 1.0104x over previous
#include <cuda_runtime.h>

#define GAMMA    0.99f
#define B_ROWS   8192
#define T1       1025
#define NSCAN    1023
#define THREADS  128
#define ITEMS    8                       // 128*8 = 1024 >= 1023
#define SKEW(j)  ((j) + ((j) >> 3))      // +1 pad per 8 floats -> stride-8 reads conflict-free
#define SMEMN    (T1 + (T1 >> 3) + 2)    // 1025 + 128 + 2

__device__ float        g_partial[B_ROWS];
__device__ unsigned int g_count = 0;     // self-resetting; graph-replay safe

// One block per row.
// Backward recurrence y[t] = b[t] + a[t]*y[t+1], y[1023] = Q[1024], scan order s=0..1022, t=1022-s.
//   a[t] = GAMMA * c(t+2),  b[t] = rew[t+1] + GAMMA*(eTQ[t+2] - c(t+2)*tQ[t+2])
//   c(j) = exp(min(tpp[j]-bpp[j], 0))
__global__ __launch_bounds__(THREADS)
void retrace_kernel(const float* __restrict__ Q,
                    const float* __restrict__ eTQ,
                    const float* __restrict__ tQ,
                    const float* __restrict__ rew,
                    const float* __restrict__ tpp,
                    const float* __restrict__ bpp,
                    float* __restrict__ out)
{
    __shared__ float  sc[SMEMN];    // GAMMA * c(j)
    __shared__ float  se[SMEMN];    // GAMMA * (eTQ[j] - c(j)*tQ[j])
    __shared__ float  srw[SMEMN];   // rew[j]
    __shared__ float  sq[SMEMN];    // Q[j]
    __shared__ float  wAs[4], wBs[4], werr[4];
    __shared__ double dred[THREADS];
    __shared__ bool   isLast;

    const int  row  = blockIdx.x;
    const int  tid  = threadIdx.x;
    const long base = (long)row * T1;

    // ---- Stage: forward, fully-coalesced loads; fold exp/c math in here ----
    for (int j = tid; j < T1; j += THREADS) {
        const float tp = tpp[base + j];
        const float bp = bpp[base + j];
        const float c  = __expf(fminf(tp - bp, 0.0f));
        const int   ji = SKEW(j);
        sc[ji]  = GAMMA * c;
        se[ji]  = GAMMA * (eTQ[base + j] - c * tQ[base + j]);
        srw[ji] = rew[base + j];
        sq[ji]  = Q[base + j];
    }
    __syncthreads();

    // ---- Phase 1: per-thread chunk of 8 scan items, compose into one affine ----
    float a[ITEMS], b[ITEMS];
    float A = 1.0f, Bc = 0.0f;
    #pragma unroll
    for (int k = 0; k < ITEMS; k++) {
        const int s = tid * ITEMS + k;
        if (s < NSCAN) {
            const int j = 1024 - s;               // j = t+2
            a[k] = sc[SKEW(j)];
            b[k] = srw[SKEW(j - 1)] + se[SKEW(j)];
        } else {                                   // identity pad (s == 1023)
            a[k] = 1.0f; b[k] = 0.0f;
        }
        Bc = fmaf(a[k], Bc, b[k]);                 // (A,B) <- f_k  o  (A,B)
        A  = a[k] * A;
    }

    // ---- Warp-level inclusive scan of affines (5 shfl steps) ----
    const int lane = tid & 31;
    const int warp = tid >> 5;
    #pragma unroll
    for (int off = 1; off < 32; off <<= 1) {
        const float pA = __shfl_up_sync(0xffffffffu, A,  off);
        const float pB = __shfl_up_sync(0xffffffffu, Bc, off);
        if (lane >= off) { Bc = fmaf(A, pB, Bc); A *= pA; }
    }
    if (lane == 31) { wAs[warp] = A; wBs[warp] = Bc; }
    __syncthreads();

    // Cross-warp exclusive prefix (<= 3 folds, in order: deterministic)
    float WA = 1.0f, WB = 0.0f;
    for (int i = 0; i < warp; i++) { WB = fmaf(wAs[i], WB, wBs[i]); WA = wAs[i] * WA; }

    // Thread-exclusive prefix = (within-warp exclusive) o (warp prefix)
    float eA = __shfl_up_sync(0xffffffffu, A,  1);
    float eB = __shfl_up_sync(0xffffffffu, Bc, 1);
    if (lane == 0) { eA = 1.0f; eB = 0.0f; }
    const float Aex = eA * WA;
    const float Bex = fmaf(eA, WB, eB);

    // ---- Phase 2: replay chunk from seed, accumulate squared error ----
    const float init = sq[SKEW(1024)];
    float y = fmaf(Aex, init, Bex);               // = Q_ret[1023 - 8*tid]

    float err = 0.0f;
    if (tid == 0) {                               // t = 1023 term: Q_ret = init
        const float d = sq[SKEW(1023)] - init;
        err = d * d;
    }
    #pragma unroll
    for (int k = 0; k < ITEMS; k++) {
        const int s = tid * ITEMS + k;
        y = fmaf(a[k], y, b[k]);                  // y = Q_ret[1022 - s]
        if (s < NSCAN) {
            const float d = sq[SKEW(1022 - s)] - y;
            err = fmaf(d, d, err);
        }
    }

    // ---- Block error reduction (deterministic) ----
    #pragma unroll
    for (int off = 16; off; off >>= 1)
        err += __shfl_xor_sync(0xffffffffu, err, off);
    if (lane == 0) werr[warp] = err;
    __syncthreads();

    if (tid == 0) {
        g_partial[row] = (werr[0] + werr[1]) + (werr[2] + werr[3]);
        __threadfence();
        const unsigned old = atomicAdd(&g_count, 1u);
        isLast = (old == (unsigned)(gridDim.x - 1));
    }
    __syncthreads();

    // ---- Last block: deterministic final mean (fixed order), reset counter ----
    if (isLast) {
        double s = 0.0;
        for (int i = tid; i < B_ROWS; i += THREADS)
            s += (double)__ldcg(&g_partial[i]);
        dred[tid] = s;
        __syncthreads();
        #pragma unroll
        for (int off = THREADS / 2; off; off >>= 1) {
            if (tid < off) dred[tid] += dred[tid + off];
            __syncthreads();
        }
        if (tid == 0) {
            out[0]  = (float)(dred[0] / ((double)B_ROWS * 1024.0));
            g_count = 0;                          // reset for next graph replay
        }
    }
}

extern "C" void kernel_launch(void* const* d_in, const int* in_sizes, int n_in,
                              void* d_out, int out_size)
{
    (void)in_sizes; (void)n_in; (void)out_size;
    const float* Q   = (const float*)d_in[0];
    const float* eTQ = (const float*)d_in[1];
    const float* tQ  = (const float*)d_in[2];
    const float* rew = (const float*)d_in[3];
    const float* tpp = (const float*)d_in[4];
    const float* bpp = (const float*)d_in[5];

    retrace_kernel<<<B_ROWS, THREADS>>>(Q, eTQ, tQ, rew, tpp, bpp, (float*)d_out);
}